// round 15
// baseline (speedup 1.0000x reference)
#include <cuda_runtime.h>
#include <cuda_bf16.h>

#define MAXN 300000
#define BR   128                 // rows per block
#define XTS  160                 // xT k-row stride (>= 128 + max swizzle 28)
#define KSWZ(k) ((((k) >> 3) & 7) * 4)   // bank swizzle per k-row

__device__ float d_g[MAXN * 64];
__device__ float d_s[MAXN * 64];
__device__ float d_deg[MAXN];
__device__ float d_dinv[MAXN];

// ---------------------------------------------------------------------------
__global__ void deg_init_kernel(float* deg, int n) {
    int i = blockIdx.x * blockDim.x + threadIdx.x;
    if (i < n) deg[i] = 1.0f;
}
__global__ void deg_count_kernel(const int* __restrict__ col, float* deg, int e) {
    int i = blockIdx.x * blockDim.x + threadIdx.x;
    if (i < e) atomicAdd(&deg[col[i]], 1.0f);
}
__global__ void dinv_kernel(const float* __restrict__ deg, float* dinv, int n) {
    int i = blockIdx.x * blockDim.x + threadIdx.x;
    if (i < n) dinv[i] = rsqrtf(deg[i]);
}

// ---------------------------------------------------------------------------
#define FFMA2(acc, x, w) \
    asm volatile("fma.rn.f32x2 %0, %1, %2, %0;" : "+l"(acc) : "l"(x), "l"(w))

__device__ __forceinline__ unsigned long long dupf2(float a) {
    unsigned long long r;
    asm("mov.b64 %0, {%1,%1};" : "=l"(r) : "f"(a));
    return r;
}

union F4U   { float4 f4; unsigned long long u[2]; };
union ULLF2 { unsigned long long u; float2 f; };

// Fused transform + GEMM + epilogue, f32x2 over COLUMN pairs (x broadcast,
// W natural — no W duplication in smem).
//  MODE 0: x = embedding gather; MODE 1: x = relu(dinv*s+b); MODE 2: final.
// Block: 128 rows x 64 cols, 256 threads. Thread tile 4 rows x 8 cols.
//  rowq = t>>3 (rows rowq*4..+3), colq = t&7 (cols colq*8..+7, contiguous).
// Per k/thread: 1 LDS.128 x + 2 LDS.128 W + 4 dup-movs + 16 FFMA2.
// smem: xT[64][XTS] (40KB) + Wn[64][64] (16KB) = 56KB -> 4 blocks/SM.
#define SMEM_FLOATS (64 * XTS + 64 * 64)

template <int MODE>
__global__ void __launch_bounds__(256, 4)
mm6_kernel(const float* __restrict__ xsrcA,
           const float* __restrict__ xsrcB,
           const int*   __restrict__ uids,
           const int*   __restrict__ iids,
           const float* __restrict__ dinv,
           const float* __restrict__ bprev,
           const float* __restrict__ W,
           const float* __restrict__ bout,
           float* __restrict__ g,
           float* __restrict__ s,
           float* __restrict__ out,
           int N, int U)
{
    extern __shared__ float smem[];
    float* xT = smem;             // xT[k*XTS + KSWZ(k) + row]
    float* Wn = smem + 64 * XTS;  // Wn[k*64 + c]  (natural)

    const int t  = threadIdx.x;
    const int r0 = blockIdx.x * BR;

    // --- Wn fill: straight float4 copy (coalesced, conflict-free) ---
    #pragma unroll
    for (int idx = t; idx < 64 * 16; idx += 256)
        *(float4*)&Wn[idx * 4] = *(const float4*)&W[idx * 4];

    // --- xT fill: coalesced row loads, transposed swizzled stores ---
    #pragma unroll
    for (int idx = t; idx < BR * 16; idx += 256) {
        int rr  = idx >> 4;          // 0..127
        int kq  = idx & 15;          // float4 index along k
        int row = r0 + rr;
        float4 v = make_float4(0.f, 0.f, 0.f, 0.f);
        if (row < N) {
            if (MODE == 0) {
                const float* src = (row < U)
                    ? &xsrcA[(long)__ldg(&uids[row]) * 64 + kq * 4]
                    : &xsrcB[(long)__ldg(&iids[row - U]) * 64 + kq * 4];
                v = *(const float4*)src;
            } else {
                float di  = __ldg(&dinv[row]);
                float4 sv = *(const float4*)&xsrcA[(long)row * 64 + kq * 4];
                float4 bv = *(const float4*)&bprev[kq * 4];
                v.x = di * sv.x + bv.x;  v.y = di * sv.y + bv.y;
                v.z = di * sv.z + bv.z;  v.w = di * sv.w + bv.w;
                if (MODE == 1) {
                    v.x = fmaxf(v.x, 0.f); v.y = fmaxf(v.y, 0.f);
                    v.z = fmaxf(v.z, 0.f); v.w = fmaxf(v.w, 0.f);
                }
            }
        }
        int k0 = 4 * kq;
        xT[(k0 + 0) * XTS + KSWZ(k0 + 0) + rr] = v.x;
        xT[(k0 + 1) * XTS + KSWZ(k0 + 1) + rr] = v.y;
        xT[(k0 + 2) * XTS + KSWZ(k0 + 2) + rr] = v.z;
        xT[(k0 + 3) * XTS + KSWZ(k0 + 3) + rr] = v.w;
    }
    __syncthreads();

    const int rowq = t >> 3;   // 0..31 -> rows rowq*4..+3
    const int colq = t & 7;    // 0..7  -> cols colq*8..+7 (contiguous)

    const float* xbase = &xT[rowq * 4];
    const float* wbase = &Wn[colq * 8];

    unsigned long long acc[4][4];   // [row i][colpair j] = cols 8colq+2j(+1)
    #pragma unroll
    for (int i = 0; i < 4; i++)
        #pragma unroll
        for (int j = 0; j < 4; j++) acc[i][j] = 0ull;

    #pragma unroll 8
    for (int k = 0; k < 64; k++) {
        float4 xv = *(const float4*)(xbase + k * XTS + KSWZ(k));  // 4 rows @ k
        F4U wa, wb;
        wa.f4 = *(const float4*)(wbase + k * 64);       // cols 8c..8c+3
        wb.f4 = *(const float4*)(wbase + k * 64 + 4);   // cols 8c+4..8c+7
        unsigned long long xd0 = dupf2(xv.x);
        unsigned long long xd1 = dupf2(xv.y);
        unsigned long long xd2 = dupf2(xv.z);
        unsigned long long xd3 = dupf2(xv.w);
        FFMA2(acc[0][0], xd0, wa.u[0]); FFMA2(acc[0][1], xd0, wa.u[1]);
        FFMA2(acc[0][2], xd0, wb.u[0]); FFMA2(acc[0][3], xd0, wb.u[1]);
        FFMA2(acc[1][0], xd1, wa.u[0]); FFMA2(acc[1][1], xd1, wa.u[1]);
        FFMA2(acc[1][2], xd1, wb.u[0]); FFMA2(acc[1][3], xd1, wb.u[1]);
        FFMA2(acc[2][0], xd2, wa.u[0]); FFMA2(acc[2][1], xd2, wa.u[1]);
        FFMA2(acc[2][2], xd2, wb.u[0]); FFMA2(acc[2][3], xd2, wb.u[1]);
        FFMA2(acc[3][0], xd3, wa.u[0]); FFMA2(acc[3][1], xd3, wa.u[1]);
        FFMA2(acc[3][2], xd3, wb.u[0]); FFMA2(acc[3][3], xd3, wb.u[1]);
    }

    // --- epilogue: 4 rows x 8 contiguous cols, float4 stores ---
    #pragma unroll
    for (int i = 0; i < 4; i++) {
        int row = r0 + rowq * 4 + i;
        if (row >= N) continue;
        ULLF2 a0, a1, a2, a3;
        a0.u = acc[i][0]; a1.u = acc[i][1]; a2.u = acc[i][2]; a3.u = acc[i][3];
        long base = (long)row * 64 + colq * 8;
        if (MODE == 2) {
            float4 bA = *(const float4*)&bout[colq * 8];
            float4 bB = *(const float4*)&bout[colq * 8 + 4];
            float4 oA = make_float4(a0.f.x + bA.x, a0.f.y + bA.y,
                                    a1.f.x + bA.z, a1.f.y + bA.w);
            float4 oB = make_float4(a2.f.x + bB.x, a2.f.y + bB.y,
                                    a3.f.x + bB.z, a3.f.y + bB.w);
            *(float4*)&out[base]     = oA;
            *(float4*)&out[base + 4] = oB;
        } else {
            float di = dinv[row];
            float4 oA = make_float4(di * a0.f.x, di * a0.f.y,
                                    di * a1.f.x, di * a1.f.y);
            float4 oB = make_float4(di * a2.f.x, di * a2.f.y,
                                    di * a3.f.x, di * a3.f.y);
            *(float4*)&g[base]     = oA;  *(float4*)&g[base + 4]     = oB;
            *(float4*)&s[base]     = oA;  *(float4*)&s[base + 4]     = oB;
        }
    }
}

// ---------------------------------------------------------------------------
// Scatter: 16 lanes per edge, LDG.128 + red.global.add.v4.f32
// ---------------------------------------------------------------------------
__global__ void __launch_bounds__(256)
scatter2_kernel(const int* __restrict__ row, const int* __restrict__ col,
                const float* __restrict__ g, float* __restrict__ s, int e)
{
    int gt   = blockIdx.x * blockDim.x + threadIdx.x;
    int eidx = gt >> 4;
    int sub  = gt & 15;
    if (eidx >= e) return;
    int r = __ldg(&row[eidx]);
    int c = __ldg(&col[eidx]);
    float4 v = __ldg((const float4*)&g[(long)r * 64 + sub * 4]);
    float* dst = &s[(long)c * 64 + sub * 4];
    asm volatile("red.global.add.v4.f32 [%0], {%1,%2,%3,%4};"
                 :: "l"(dst), "f"(v.x), "f"(v.y), "f"(v.z), "f"(v.w)
                 : "memory");
}

// ---------------------------------------------------------------------------
extern "C" void kernel_launch(void* const* d_in, const int* in_sizes, int n_in,
                              void* d_out, int out_size)
{
    const int*   user_ids   = (const int*)  d_in[0];
    const int*   item_ids   = (const int*)  d_in[1];
    const int*   edge_index = (const int*)  d_in[2];
    const float* user_table = (const float*)d_in[4];
    const float* item_table = (const float*)d_in[5];
    const float* W1 = (const float*)d_in[6];
    const float* b1 = (const float*)d_in[7];
    const float* W2 = (const float*)d_in[8];
    const float* b2 = (const float*)d_in[9];
    const float* W3 = (const float*)d_in[10];
    const float* b3 = (const float*)d_in[11];
    const float* lin_W = (const float*)d_in[12];
    const float* lin_b = (const float*)d_in[13];
    float* out = (float*)d_out;

    const int U = in_sizes[0];
    const int I = in_sizes[1];
    const int N = U + I;
    const int E = in_sizes[2] / 2;
    const int* erow = edge_index;
    const int* ecol = edge_index + E;

    float *g, *s, *deg, *dinv;
    cudaGetSymbolAddress((void**)&g,    d_g);
    cudaGetSymbolAddress((void**)&s,    d_s);
    cudaGetSymbolAddress((void**)&deg,  d_deg);
    cudaGetSymbolAddress((void**)&dinv, d_dinv);

    const size_t smemB = SMEM_FLOATS * sizeof(float);
    static bool attrSet = false;
    if (!attrSet) {
        cudaFuncSetAttribute(mm6_kernel<0>, cudaFuncAttributeMaxDynamicSharedMemorySize, (int)smemB);
        cudaFuncSetAttribute(mm6_kernel<1>, cudaFuncAttributeMaxDynamicSharedMemorySize, (int)smemB);
        cudaFuncSetAttribute(mm6_kernel<2>, cudaFuncAttributeMaxDynamicSharedMemorySize, (int)smemB);
        attrSet = true;
    }

    const int mmBlocks = (N + BR - 1) / BR;
    const int scBlocks = (E * 16 + 255) / 256;
    const int nB = (N + 255) / 256;
    const int eB = (E + 255) / 256;

    deg_init_kernel<<<nB, 256>>>(deg, N);
    deg_count_kernel<<<eB, 256>>>(ecol, deg, E);
    dinv_kernel<<<nB, 256>>>(deg, dinv, N);

    mm6_kernel<0><<<mmBlocks, 256, smemB>>>(user_table, item_table, user_ids, item_ids,
                                            dinv, nullptr, W1, nullptr, g, s, nullptr, N, U);
    scatter2_kernel<<<scBlocks, 256>>>(erow, ecol, g, s, E);

    mm6_kernel<1><<<mmBlocks, 256, smemB>>>(s, nullptr, nullptr, nullptr,
                                            dinv, b1, W2, nullptr, g, s, nullptr, N, U);
    scatter2_kernel<<<scBlocks, 256>>>(erow, ecol, g, s, E);

    mm6_kernel<1><<<mmBlocks, 256, smemB>>>(s, nullptr, nullptr, nullptr,
                                            dinv, b2, W3, nullptr, g, s, nullptr, N, U);
    scatter2_kernel<<<scBlocks, 256>>>(erow, ecol, g, s, E);

    mm6_kernel<2><<<mmBlocks, 256, smemB>>>(s, nullptr, nullptr, nullptr,
                                            dinv, b3, lin_W, lin_b, nullptr, nullptr, out, N, U);
}